// round 3
// baseline (speedup 1.0000x reference)
#include <cuda_runtime.h>

// QKVAttentionWithRelativePosition — fused flash-style fp32 kernel.
// B=8, H=8, D=64, L=512.
//   logits[b,h,i,j] = sum_d q[i,d]*(k[j,d] + k_emb[h, j-i+L-1, d])
//   out = softmax_j(logits) @ v, emitted in raw [B,H,L,D] flat order
//   (reference's reshape(B,-1,L) is a raw reshape, so bytes match).

#define NH       8
#define LSEQ     512
#define DH       64
#define BM       64
#define ESTRIDE  132   // emb smem row stride (mult of 4 for float4 align)
#define VSTRIDE  65    // v smem row stride (conflict-free both ways)

#define SM_FLOATS (64*64 /*q*/ + 64*64 /*k*/ + 64*VSTRIDE /*v*/ + 64*64 /*p*/ + 64*ESTRIDE /*emb*/)
#define SM_BYTES  (SM_FLOATS * 4)

__global__ __launch_bounds__(256, 2)
void attn_rel_kernel(const float* __restrict__ qkv,
                     const float* __restrict__ kemb,
                     float* __restrict__ out)
{
    extern __shared__ float sm[];
    float* q_s = sm;                    // [d][i]   64x64
    float* k_s = q_s + 64 * 64;         // [d][j]   64x64
    float* v_s = k_s + 64 * 64;         // [j][d]   64x65
    float* p_s = v_s + 64 * VSTRIDE;    // [i][j]   64x64
    float* e_s = p_s + 64 * 64;         // [d][mm]  64x132 (127 valid mm)

    const int tid = threadIdx.x;
    const int tx  = tid & 15;           // column group (j / d in epilogue)
    const int ty  = tid >> 4;           // row group (i)
    const int i0  = blockIdx.x * BM;
    const int h   = blockIdx.y;
    const int b   = blockIdx.z;

    const size_t base_q = ((size_t)b * (3 * NH * DH) + (size_t)h * (3 * DH)) * LSEQ;
    const size_t base_k = base_q + (size_t)DH * LSEQ;
    const size_t base_v = base_q + (size_t)(2 * DH) * LSEQ;

    // ---- load Q tile: q_s[d][i], coalesced over i ----
    {
        const int li = tid & 63;
        const int d0 = tid >> 6;
        #pragma unroll
        for (int r = 0; r < 16; r++) {
            const int d = d0 + 4 * r;
            q_s[d * 64 + li] = qkv[base_q + (size_t)d * LSEQ + i0 + li];
        }
    }

    float m_r[4], l_r[4], o_r[4][4];
    #pragma unroll
    for (int a = 0; a < 4; a++) {
        m_r[a] = -1e30f;
        l_r[a] = 0.0f;
        #pragma unroll
        for (int c = 0; c < 4; c++) o_r[a][c] = 0.0f;
    }

    // emb smem offset base for this thread's 4x4 tile:
    // mm = (j - i) + 63; thread covers mm in [4(tx-ty)+60, 4(tx-ty)+66]
    const int ebase = 4 * (tx - ty) + 60;

    for (int jt = 0; jt < LSEQ / 64; jt++) {
        const int j0 = jt * 64;

        // ---- load K and V tiles (coalesced over j) ----
        {
            const int lj = tid & 63;
            const int d0 = tid >> 6;
            #pragma unroll
            for (int r = 0; r < 16; r++) {
                const int d = d0 + 4 * r;
                const float kv = qkv[base_k + (size_t)d * LSEQ + j0 + lj];
                const float vv = qkv[base_v + (size_t)d * LSEQ + j0 + lj];
                k_s[d * 64 + lj]        = kv;   // [d][j]
                v_s[lj * VSTRIDE + d]   = vv;   // [j][d], stride-65 write: conflict-free
            }
        }
        // ---- load emb window: e_s[d][mm] = k_emb[h, mbase+mm, d], mm<127 ----
        {
            const int d   = tid & 63;
            const int mm0 = tid >> 6;
            const int mbase = j0 - i0 + (LSEQ - 64);          // in [0, 896]
            const size_t gb = ((size_t)h * (2 * LSEQ - 1) + mbase) * DH + d;
            #pragma unroll
            for (int r = 0; r < 32; r++) {
                const int mm = mm0 + 4 * r;
                if (mm < 127)
                    e_s[d * ESTRIDE + mm] = kemb[gb + (size_t)mm * DH];
            }
        }
        __syncthreads();

        // ---- logits: acc[a][c] = sum_d q * (k + emb) ----
        float acc[4][4];
        #pragma unroll
        for (int a = 0; a < 4; a++)
            #pragma unroll
            for (int c = 0; c < 4; c++) acc[a][c] = 0.0f;

        #pragma unroll 8
        for (int d = 0; d < 64; d++) {
            const float4 qv = *(const float4*)(q_s + d * 64 + 4 * ty);
            const float4 kv = *(const float4*)(k_s + d * 64 + 4 * tx);
            const float4 ea = *(const float4*)(e_s + d * ESTRIDE + ebase);
            const float4 eb = *(const float4*)(e_s + d * ESTRIDE + ebase + 4);
            const float qa[4] = {qv.x, qv.y, qv.z, qv.w};
            const float kb[4] = {kv.x, kv.y, kv.z, kv.w};
            const float ev[8] = {ea.x, ea.y, ea.z, ea.w, eb.x, eb.y, eb.z, eb.w};
            #pragma unroll
            for (int a = 0; a < 4; a++)
                #pragma unroll
                for (int c = 0; c < 4; c++)
                    acc[a][c] = fmaf(qa[a], kb[c] + ev[c - a + 3], acc[a][c]);
        }

        // ---- online softmax update (row stats shared across the 16 tx lanes) ----
        #pragma unroll
        for (int a = 0; a < 4; a++) {
            float tmax = fmaxf(fmaxf(acc[a][0], acc[a][1]), fmaxf(acc[a][2], acc[a][3]));
            #pragma unroll
            for (int off = 1; off < 16; off <<= 1)
                tmax = fmaxf(tmax, __shfl_xor_sync(0xffffffffu, tmax, off));
            const float mnew = fmaxf(m_r[a], tmax);
            const float corr = __expf(m_r[a] - mnew);
            float rsum = 0.0f;
            #pragma unroll
            for (int c = 0; c < 4; c++) {
                const float p = __expf(acc[a][c] - mnew);
                acc[a][c] = p;
                rsum += p;
            }
            #pragma unroll
            for (int off = 1; off < 16; off <<= 1)
                rsum += __shfl_xor_sync(0xffffffffu, rsum, off);
            l_r[a] = l_r[a] * corr + rsum;
            m_r[a] = mnew;
            #pragma unroll
            for (int c = 0; c < 4; c++) o_r[a][c] *= corr;
            *(float4*)(p_s + (4 * ty + a) * 64 + 4 * tx) =
                make_float4(acc[a][0], acc[a][1], acc[a][2], acc[a][3]);
        }
        __syncthreads();

        // ---- AV: o_r[a][c] += p[i][j] * v[j][d] ----
        #pragma unroll 4
        for (int j = 0; j < 64; j += 4) {
            float pr[4][4];
            #pragma unroll
            for (int a = 0; a < 4; a++) {
                const float4 t = *(const float4*)(p_s + (4 * ty + a) * 64 + j);
                pr[a][0] = t.x; pr[a][1] = t.y; pr[a][2] = t.z; pr[a][3] = t.w;
            }
            #pragma unroll
            for (int jj = 0; jj < 4; jj++) {
                float vv[4];
                #pragma unroll
                for (int c = 0; c < 4; c++)
                    vv[c] = v_s[(j + jj) * VSTRIDE + 4 * tx + c];
                #pragma unroll
                for (int a = 0; a < 4; a++)
                    #pragma unroll
                    for (int c = 0; c < 4; c++)
                        o_r[a][c] = fmaf(pr[a][jj], vv[c], o_r[a][c]);
            }
        }
        __syncthreads();   // protect k_s/v_s/e_s/p_s before next tile's loads
    }

    // ---- epilogue: normalize and store in raw [B,H,L,D] flat order ----
    const size_t ob = (((size_t)b * NH + h) * LSEQ + i0) * DH;
    #pragma unroll
    for (int a = 0; a < 4; a++) {
        const float inv = 1.0f / l_r[a];
        *(float4*)(out + ob + (size_t)(4 * ty + a) * DH + 4 * tx) =
            make_float4(o_r[a][0] * inv, o_r[a][1] * inv,
                        o_r[a][2] * inv, o_r[a][3] * inv);
    }
}

extern "C" void kernel_launch(void* const* d_in, const int* in_sizes, int n_in,
                              void* d_out, int out_size)
{
    const float* qkv  = (const float*)d_in[0];
    const float* kemb = (const float*)d_in[1];
    // d_in[2] (v_emb) is unused by the reference (add_relative_to_values=False)
    float* out = (float*)d_out;

    const int B = in_sizes[0] / (3 * NH * DH * LSEQ);   // = 8

    cudaFuncSetAttribute(attn_rel_kernel,
                         cudaFuncAttributeMaxDynamicSharedMemorySize, SM_BYTES);

    dim3 grid(LSEQ / BM, NH, B);   // (8, 8, 8)
    attn_rel_kernel<<<grid, 256, SM_BYTES>>>(qkv, kemb, out);
}

// round 5
// speedup vs baseline: 1.2266x; 1.2266x over previous
#include <cuda_runtime.h>

// QKVAttentionWithRelativePosition — fused flash-style fp32 kernel, f32x2 math.
// B=8, H=8, D=64, L=512.
//   logits[b,h,i,j] = sum_d q[i,d]*(k[j,d] + k_emb[h, j-i+L-1, d])
//   out = softmax_j(logits) @ v, raw [B,H,L,D] flat order.

#define NH       8
#define LSEQ     512
#define DH       64
#define BM       128
#define BN       128
#define ESTRIDE  264    // mult of 8 floats -> 32B-aligned rows for paired loads
#define VSTRIDE  68
#define PSTRIDE  128

typedef unsigned long long ull;

__device__ __forceinline__ ull pack2(float x, float y) {
    ull r; asm("mov.b64 %0, {%1, %2};" : "=l"(r) : "f"(x), "f"(y)); return r;
}
__device__ __forceinline__ void unpack2(ull v, float& x, float& y) {
    asm("mov.b64 {%0, %1}, %2;" : "=f"(x), "=f"(y) : "l"(v));
}
__device__ __forceinline__ ull add2(ull a, ull b) {
    ull r; asm("add.rn.f32x2 %0, %1, %2;" : "=l"(r) : "l"(a), "l"(b)); return r;
}
__device__ __forceinline__ ull mul2(ull a, ull b) {
    ull r; asm("mul.rn.f32x2 %0, %1, %2;" : "=l"(r) : "l"(a), "l"(b)); return r;
}
__device__ __forceinline__ ull fma2(ull a, ull b, ull c) {
    ull r; asm("fma.rn.f32x2 %0, %1, %2, %3;" : "=l"(r) : "l"(a), "l"(b), "l"(c)); return r;
}

// smem: q 64x128 | k 64x128 | v 128x68 | union(e 64x264, p 128x128)
#define SM_FLOATS (64*BM + 64*BN + BN*VSTRIDE + 64*ESTRIDE)
#define SM_BYTES  (SM_FLOATS * 4)

__global__ __launch_bounds__(256, 1)
void attn_rel_kernel(const float* __restrict__ qkv,
                     const float* __restrict__ kemb,
                     float* __restrict__ out)
{
    extern __shared__ float sm[];
    float* q_s = sm;                         // [d][i]
    float* k_s = q_s + 64 * BM;              // [d][j]
    float* v_s = k_s + 64 * BN;              // [j][d]
    float* e_s = v_s + BN * VSTRIDE;         // [d][mm], mm<255
    float* p_s = e_s;                        // alias: [i][j] (phases disjoint)

    const int tid = threadIdx.x;
    const int tx  = tid & 15;
    const int ty  = tid >> 4;
    const int i0  = blockIdx.x * BM;
    const int h   = blockIdx.y;
    const int b   = blockIdx.z;

    const size_t base_q = ((size_t)b * (3 * NH * DH) + (size_t)h * (3 * DH)) * LSEQ;
    const size_t base_k = base_q + (size_t)DH * LSEQ;
    const size_t base_v = base_q + (size_t)(2 * DH) * LSEQ;

    // ---- Q tile once: q_s[d][i], coalesced over i ----
    {
        const int li = tid & 127, d0 = tid >> 7;
        const float* src = qkv + base_q + i0 + li;
        #pragma unroll
        for (int r = 0; r < 32; r++) {
            const int d = d0 + 2 * r;
            q_s[d * BM + li] = src[(size_t)d * LSEQ];
        }
    }

    float m_r[8], l_r[8];
    ull o2[8][2];
    #pragma unroll
    for (int a = 0; a < 8; a++) {
        m_r[a] = -1e30f; l_r[a] = 0.0f;
        o2[a][0] = 0ull; o2[a][1] = 0ull;
    }

    // thread (a,c): mm = (8tx+c)-(8ty+a)+127 = ebase + (c-a+7), window w in [0,14]
    const int ebase = 8 * (tx - ty) + 120;           // in [0, 240]
    const float* qp = q_s + 8 * ty;
    const float* kp = k_s + 8 * tx;
    const float* ep = e_s + ebase;
    const float* vp = v_s + 4 * tx;
    float* pw = p_s + (8 * ty) * PSTRIDE + 8 * tx;   // p store base
    const float* pr = p_s + (8 * ty) * PSTRIDE;      // p read base

    for (int jt = 0; jt < LSEQ / BN; jt++) {
        const int j0 = jt * BN;
        if (jt) __syncthreads();                     // AV(prev) done before overwriting tiles

        // ---- load K,V (coalesced over j) ----
        {
            const int lj = tid & 127, d0 = tid >> 7;
            const float* srck = qkv + base_k + j0 + lj;
            const float* srcv = qkv + base_v + j0 + lj;
            #pragma unroll
            for (int r = 0; r < 32; r++) {
                const int d = d0 + 2 * r;
                const float kv = srck[(size_t)d * LSEQ];
                const float vv = srcv[(size_t)d * LSEQ];
                k_s[d * BN + lj]      = kv;
                v_s[lj * VSTRIDE + d] = vv;
            }
        }
        // ---- load emb window: e_s[d][mm] = kemb[h, mbase+mm, d], mm<255 ----
        {
            const int de = tid & 63, g = tid >> 6;
            const int mbase = j0 - i0 + 384;         // in [0, 768]
            const float* srce = kemb + (size_t)h * (2 * LSEQ - 1) * DH + (size_t)mbase * DH + de;
            #pragma unroll
            for (int r = 0; r < 16; r++) {
                const int mm0 = 4 * (g + 4 * r);     // 0..252
                float4 v4;
                v4.x = srce[(size_t)(mm0 + 0) * DH];
                v4.y = srce[(size_t)(mm0 + 1) * DH];
                v4.z = srce[(size_t)(mm0 + 2) * DH];
                v4.w = (mm0 + 3 < 255) ? srce[(size_t)(mm0 + 3) * DH] : 0.0f;
                *(float4*)(e_s + de * ESTRIDE + mm0) = v4;
            }
        }
        __syncthreads();

        // ---- logits: acc2[a][c2] += {q,q} * (k2 + e2), packed over j ----
        ull acc[8][4];
        #pragma unroll
        for (int a = 0; a < 8; a++)
            #pragma unroll
            for (int c = 0; c < 4; c++) acc[a][c] = 0ull;

        #pragma unroll 4
        for (int d = 0; d < 64; d++) {
            const float4 qa4 = *(const float4*)(qp + d * BM);
            const float4 qb4 = *(const float4*)(qp + d * BM + 4);
            const ulonglong2 kk0 = *(const ulonglong2*)(kp + d * BN);
            const ulonglong2 kk1 = *(const ulonglong2*)(kp + d * BN + 4);
            const float4 e0 = *(const float4*)(ep + d * ESTRIDE);
            const float4 e1 = *(const float4*)(ep + d * ESTRIDE + 4);
            const float4 e2v = *(const float4*)(ep + d * ESTRIDE + 8);
            const float4 e3 = *(const float4*)(ep + d * ESTRIDE + 12);
            const float ev[16] = {e0.x, e0.y, e0.z, e0.w, e1.x, e1.y, e1.z, e1.w,
                                  e2v.x, e2v.y, e2v.z, e2v.w, e3.x, e3.y, e3.z, e3.w};
            ull pe[8], po[7];
            #pragma unroll
            for (int m = 0; m < 8; m++) pe[m] = pack2(ev[2 * m],     ev[2 * m + 1]);
            #pragma unroll
            for (int m = 0; m < 7; m++) po[m] = pack2(ev[2 * m + 1], ev[2 * m + 2]);
            const ull k2[4] = {kk0.x, kk0.y, kk1.x, kk1.y};
            const float qs[8] = {qa4.x, qa4.y, qa4.z, qa4.w, qb4.x, qb4.y, qb4.z, qb4.w};
            #pragma unroll
            for (int a = 0; a < 8; a++) {
                const ull qq = pack2(qs[a], qs[a]);
                #pragma unroll
                for (int c2 = 0; c2 < 4; c2++) {
                    const int m = 2 * c2 + 7 - a;     // window index, compile-time
                    const ull epair = (m & 1) ? po[(m - 1) >> 1] : pe[m >> 1];
                    acc[a][c2] = fma2(qq, add2(k2[c2], epair), acc[a][c2]);
                }
            }
        }
        __syncthreads();   // all e reads done -> p may overwrite e region

        // ---- online softmax (rows spread over 16 tx lanes) + store p ----
        #pragma unroll
        for (int a = 0; a < 8; a++) {
            float s[8];
            unpack2(acc[a][0], s[0], s[1]);
            unpack2(acc[a][1], s[2], s[3]);
            unpack2(acc[a][2], s[4], s[5]);
            unpack2(acc[a][3], s[6], s[7]);
            float tmax = s[0];
            #pragma unroll
            for (int c = 1; c < 8; c++) tmax = fmaxf(tmax, s[c]);
            #pragma unroll
            for (int off = 1; off < 16; off <<= 1)
                tmax = fmaxf(tmax, __shfl_xor_sync(0xffffffffu, tmax, off));
            const float mnew = fmaxf(m_r[a], tmax);
            const float corr = __expf(m_r[a] - mnew);
            float rsum = 0.0f;
            #pragma unroll
            for (int c = 0; c < 8; c++) { s[c] = __expf(s[c] - mnew); rsum += s[c]; }
            #pragma unroll
            for (int off = 1; off < 16; off <<= 1)
                rsum += __shfl_xor_sync(0xffffffffu, rsum, off);
            l_r[a] = l_r[a] * corr + rsum;
            m_r[a] = mnew;
            const ull c2p = pack2(corr, corr);
            o2[a][0] = mul2(o2[a][0], c2p);
            o2[a][1] = mul2(o2[a][1], c2p);
            *(float4*)(pw + a * PSTRIDE)     = make_float4(s[0], s[1], s[2], s[3]);
            *(float4*)(pw + a * PSTRIDE + 4) = make_float4(s[4], s[5], s[6], s[7]);
        }
        __syncthreads();

        // ---- AV: o2[a][c2] += {p,p} * v2, packed over d ----
        #pragma unroll 2
        for (int jg = 0; jg < BN; jg += 4) {
            float4 pa[8];
            #pragma unroll
            for (int a = 0; a < 8; a++)
                pa[a] = *(const float4*)(pr + a * PSTRIDE + jg);
            #pragma unroll
            for (int jj = 0; jj < 4; jj++) {
                const ulonglong2 vv = *(const ulonglong2*)(vp + (jg + jj) * VSTRIDE);
                #pragma unroll
                for (int a = 0; a < 8; a++) {
                    const float pv = (jj == 0) ? pa[a].x : (jj == 1) ? pa[a].y
                                   : (jj == 2) ? pa[a].z : pa[a].w;
                    const ull ppk = pack2(pv, pv);
                    o2[a][0] = fma2(ppk, vv.x, o2[a][0]);
                    o2[a][1] = fma2(ppk, vv.y, o2[a][1]);
                }
            }
        }
    }

    // ---- epilogue: normalize, store raw [B,H,L,D] flat ----
    const size_t ob = (((size_t)b * NH + h) * LSEQ + i0) * DH;
    #pragma unroll
    for (int a = 0; a < 8; a++) {
        const float inv = 1.0f / l_r[a];
        float x0, x1, x2, x3;
        unpack2(o2[a][0], x0, x1);
        unpack2(o2[a][1], x2, x3);
        *(float4*)(out + ob + (size_t)(8 * ty + a) * DH + 4 * tx) =
            make_float4(x0 * inv, x1 * inv, x2 * inv, x3 * inv);
    }
}

extern "C" void kernel_launch(void* const* d_in, const int* in_sizes, int n_in,
                              void* d_out, int out_size)
{
    const float* qkv  = (const float*)d_in[0];
    const float* kemb = (const float*)d_in[1];
    // d_in[2] (v_emb) unused by reference (add_relative_to_values=False)
    float* out = (float*)d_out;

    const int B = in_sizes[0] / (3 * NH * DH * LSEQ);   // = 8

    cudaFuncSetAttribute(attn_rel_kernel,
                         cudaFuncAttributeMaxDynamicSharedMemorySize, SM_BYTES);

    dim3 grid(LSEQ / BM, NH, B);   // (4, 8, 8)
    attn_rel_kernel<<<grid, 256, SM_BYTES>>>(qkv, kemb, out);
}